// round 6
// baseline (speedup 1.0000x reference)
#include <cuda_runtime.h>

#define HH 16
#define VV 4
#define BB 512
#define SS 8192
#define SQ (SS/4)
#define WPB 4                 // warps per block, 1 batch element per warp
#define NTHREADS (WPB*32)     // 128
#define NBLOCKS (BB/WPB)      // 128 blocks

__device__ float  g_loss[BB];
__device__ float4 g_logits[BB*SQ*VV];   // 64 MB: [b][t4][v] -> 4 steps' logits

typedef unsigned long long u64;

__device__ __forceinline__ float tanh_ap(float x){ float y; asm("tanh.approx.f32 %0, %1;" : "=f"(y) : "f"(x)); return y; }
__device__ __forceinline__ u64 pk(float lo, float hi){ u64 d; asm("mov.b64 %0,{%1,%2};" : "=l"(d) : "f"(lo), "f"(hi)); return d; }
__device__ __forceinline__ u64 fma2(u64 a, u64 b, u64 c){ u64 d; asm("fma.rn.f32x2 %0,%1,%2,%3;" : "=l"(d) : "l"(a), "l"(b), "l"(c)); return d; }
__device__ __forceinline__ u64 add2(u64 a, u64 b){ u64 d; asm("add.rn.f32x2 %0,%1,%2;" : "=l"(d) : "l"(a), "l"(b)); return d; }
__device__ __forceinline__ float hadd(u64 a){ float x,y; asm("mov.b64 {%0,%1},%2;" : "=f"(x), "=f"(y) : "l"(a)); return x+y; }
__device__ __forceinline__ float f4c(float4 v, int u){ return u==0?v.x:(u==1?v.y:(u==2?v.z:v.w)); }

__device__ __forceinline__ void sts_h(unsigned addr, float v){
    asm volatile("st.shared.b32 [%0], %1;" :: "r"(addr), "f"(v));
}
// load this lane's half of h: 4 u64 (8 floats)
__device__ __forceinline__ void ldh2(unsigned addr, u64& h0, u64& h1, u64& h2, u64& h3){
    asm volatile("ld.shared.v2.b64 {%0,%1},[%2];"    : "=l"(h0), "=l"(h1) : "r"(addr));
    asm volatile("ld.shared.v2.b64 {%0,%1},[%2+16];" : "=l"(h2), "=l"(h3) : "r"(addr));
}

// ---------------------------------------------------------------------------
// Fused encoder + decoder recurrence. One batch element per warp (32 lanes).
// Unit j = lane&15; half = lane>>4 owns k-range [8*half, 8*half+8).
// Dot products are split across halves, combined with one shfl.xor(16).
// ---------------------------------------------------------------------------
__global__ void __launch_bounds__(NTHREADS, 1)
rnn_kernel(const float* __restrict__ gt,
           const float* __restrict__ eWih, const float* __restrict__ eWhh,
           const float* __restrict__ ebih, const float* __restrict__ ebhh,
           const float* __restrict__ dWih, const float* __restrict__ dWhh,
           const float* __restrict__ dbih, const float* __restrict__ dbhh,
           const float* __restrict__ oW,  const float* __restrict__ ob)
{
    __shared__ __align__(16) float sh[WPB*16];
    const int lane = threadIdx.x & 31;
    const int w    = threadIdx.x >> 5;
    const int j    = lane & 15;
    const int half = lane >> 4;
    const int ko   = half * 8;             // this lane's k-range start
    const int b    = blockIdx.x * WPB + w;
    const unsigned hbase = (unsigned)__cvta_generic_to_shared(&sh[w*16]);
    const unsigned hhalf = hbase + (unsigned)(half*32);

    const float4* gp = (const float4*)(gt + (size_t)b * VV * SS);
    const u64 z2 = 0ULL;
    const unsigned FULL = 0xffffffffu;

    float hme = 0.f;

    // =================== ENCODER ===================
    {
        // recurrent weights for this lane's k-half (0.5-scaled for tanh-sigmoid / pre-halved n)
        u64 wr[4], wz[4], wn[4];
#pragma unroll
        for (int p = 0; p < 4; p++) {
            int k = ko + 2*p;
            wr[p] = pk(0.5f*eWhh[j*16 + k],      0.5f*eWhh[j*16 + k+1]);
            wz[p] = pk(0.5f*eWhh[(16+j)*16 + k], 0.5f*eWhh[(16+j)*16 + k+1]);
            wn[p] = pk(0.5f*eWhh[(32+j)*16 + k], 0.5f*eWhh[(32+j)*16 + k+1]);
        }
        const u64 xr01 = pk(0.5f*eWih[j*4+0],      0.5f*eWih[j*4+1]);
        const u64 xr23 = pk(0.5f*eWih[j*4+2],      0.5f*eWih[j*4+3]);
        const u64 xz01 = pk(0.5f*eWih[(16+j)*4+0], 0.5f*eWih[(16+j)*4+1]);
        const u64 xz23 = pk(0.5f*eWih[(16+j)*4+2], 0.5f*eWih[(16+j)*4+3]);
        const u64 xn01 = pk(     eWih[(32+j)*4+0],      eWih[(32+j)*4+1]);
        const u64 xn23 = pk(     eWih[(32+j)*4+2],      eWih[(32+j)*4+3]);
        const u64 brpk  = pk(0.5f*(ebih[j]    + ebhh[j]),    0.f);
        const u64 bzpk  = pk(0.5f*(ebih[16+j] + ebhh[16+j]), 0.f);
        const u64 binpk = pk(ebih[32+j], 0.f);
        const u64 bhn_l = half ? z2 : pk(0.5f*ebhh[32+j], 0.f);   // counted once

        u64 h0 = 0, h1 = 0, h2 = 0, h3 = 0;   // h0 = 0 (this lane's half)

        float4 c0 = gp[0], c1 = gp[SQ], c2 = gp[2*SQ], c3 = gp[3*SQ];

        for (int t4 = 0; t4 < SQ; ++t4) {
            int tn = t4 + 1 < SQ ? t4 + 1 : t4;
            float4 nx0 = gp[tn], nx1 = gp[SQ + tn], nx2 = gp[2*SQ + tn], nx3 = gp[3*SQ + tn];
#pragma unroll
            for (int u = 0; u < 4; u++) {
                u64 px01 = pk(f4c(c0,u), f4c(c1,u));
                u64 px23 = pk(f4c(c2,u), f4c(c3,u));
                // x-path inits (only half 0 contributes to the butterflied sum)
                u64 ri = fma2(px23, xr23, fma2(px01, xr01, brpk));
                u64 zi = fma2(px23, xz23, fma2(px01, xz01, bzpk));
                if (half) { ri = z2; zi = z2; }
                float gin = hadd(fma2(px23, xn23, fma2(px01, xn01, binpk))); // full, per lane

                // half-dots (4 fma2 each)
                u64 ra = fma2(h0, wr[0], ri); u64 rb = fma2(h1, wr[1], z2);
                ra = fma2(h2, wr[2], ra);     rb = fma2(h3, wr[3], rb);
                float srh = hadd(add2(ra, rb));
                float sr  = srh + __shfl_xor_sync(FULL, srh, 16);

                u64 za = fma2(h0, wz[0], zi); u64 zb = fma2(h1, wz[1], z2);
                za = fma2(h2, wz[2], za);     zb = fma2(h3, wz[3], zb);
                float szh = hadd(add2(za, zb));
                float sz  = szh + __shfl_xor_sync(FULL, szh, 16);

                u64 na = fma2(h0, wn[0], bhn_l); u64 nb = fma2(h1, wn[1], z2);
                na = fma2(h2, wn[2], na);        nb = fma2(h3, wn[3], nb);
                float gnh = hadd(add2(na, nb));
                float ghn = gnh + __shfl_xor_sync(FULL, gnh, 16);  // = 0.5*(h·Whn+bhn)

                float tr  = tanh_ap(sr);
                float tz  = tanh_ap(sz);
                float zg  = fmaf(tz,  0.5f, 0.5f);
                float omz = fmaf(tz, -0.5f, 0.5f);
                float zh  = zg * hme;
                float n = tanh_ap(fmaf(tr, ghn, gin + ghn));
                hme = fmaf(n, omz, zh);
                if (lane < 16) sts_h(hbase + j*4, hme);
                ldh2(hhalf, h0, h1, h2, h3);
            }
            c0 = nx0; c1 = nx1; c2 = nx2; c3 = nx3;
        }
    }

    // =================== DECODER ===================
    {
        const int v = j & 3;
        u64 wr[4], wz[4], wn[4], ow[4];
#pragma unroll
        for (int p = 0; p < 4; p++) {
            int k = ko + 2*p;
            wr[p] = pk(0.5f*dWhh[j*16 + k],      0.5f*dWhh[j*16 + k+1]);
            wz[p] = pk(0.5f*dWhh[(16+j)*16 + k], 0.5f*dWhh[(16+j)*16 + k+1]);
            wn[p] = pk(0.5f*dWhh[(32+j)*16 + k], 0.5f*dWhh[(32+j)*16 + k+1]);
            ow[p] = pk(oW[v*16 + k], oW[v*16 + k+1]);
        }
        const float br   = 0.5f*(dbih[j]    + dbhh[j]);
        const float bz   = 0.5f*(dbih[16+j] + dbhh[16+j]);
        const float bin_ = dbih[32+j];
        const u64 bhn_l = half ? z2 : pk(0.5f*dbhh[32+j], 0.f);
        const u64 ob_l  = half ? z2 : pk(ob[v], 0.f);

        float crc[4], czc[4], cnc[4];
#pragma unroll
        for (int c = 0; c < 4; c++) {
            crc[c] = br   + 0.5f*dWih[j*4 + c];
            czc[c] = bz   + 0.5f*dWih[(16+j)*4 + c];
            cnc[c] = bin_ +      dWih[(32+j)*4 + c];
        }
        float cr = br, cz = bz, cn = bin_;     // t=0: x = 0

        u64 h0, h1, h2, h3;
        if (lane < 16) sts_h(hbase + j*4, hme);
        ldh2(hhalf, h0, h1, h2, h3);           // enc hidden (this half)

        float4* lp = &g_logits[(size_t)b * SQ * VV];
        float4 lreg;

        for (int t4 = 0; t4 < SQ; ++t4) {
#pragma unroll
            for (int u = 0; u < 4; u++) {
                // gates from h_t; feedback scalar added pre-butterfly (own half only)
                u64 ra = fma2(h0, wr[0], z2); u64 rb = fma2(h1, wr[1], z2);
                ra = fma2(h2, wr[2], ra);     rb = fma2(h3, wr[3], rb);
                float srh = hadd(add2(ra, rb));
                float sr  = (srh + cr) + __shfl_xor_sync(FULL, srh, 16);

                u64 za = fma2(h0, wz[0], z2); u64 zb = fma2(h1, wz[1], z2);
                za = fma2(h2, wz[2], za);     zb = fma2(h3, wz[3], zb);
                float szh = hadd(add2(za, zb));
                float sz  = (szh + cz) + __shfl_xor_sync(FULL, szh, 16);

                u64 na = fma2(h0, wn[0], bhn_l); u64 nb = fma2(h1, wn[1], z2);
                na = fma2(h2, wn[2], na);        nb = fma2(h3, wn[3], nb);
                float gnh = hadd(add2(na, nb));
                float ghn = gnh + __shfl_xor_sync(FULL, gnh, 16);

                float tr  = tanh_ap(sr);
                float tz  = tanh_ap(sz);
                float zg  = fmaf(tz,  0.5f, 0.5f);
                float omz = fmaf(tz, -0.5f, 0.5f);
                float zh  = zg * hme;
                float n = tanh_ap(fmaf(tr, ghn, cn + ghn));
                hme = fmaf(n, omz, zh);
                if (lane < 16) sts_h(hbase + j*4, hme);
                ldh2(hhalf, h0, h1, h2, h3);     // h_{t+1}

                // logit for class v (half-dot + butterfly; ob in half0 init)
                u64 oa = fma2(h0, ow[0], ob_l); u64 obx = fma2(h1, ow[1], z2);
                oa = fma2(h2, ow[2], oa);       obx = fma2(h3, ow[3], obx);
                float oh = hadd(add2(oa, obx));
                float outv = oh + __shfl_xor_sync(FULL, oh, 16);

                if (u == 0) lreg.x = outv;
                else if (u == 1) lreg.y = outv;
                else if (u == 2) lreg.z = outv;
                else lreg.w = outv;

                float l0 = __shfl_sync(FULL, outv, 0, 4);
                float l1 = __shfl_sync(FULL, outv, 1, 4);
                float l2 = __shfl_sync(FULL, outv, 2, 4);
                float l3 = __shfl_sync(FULL, outv, 3, 4);

                // argmax (first-max) -> feedback select
                bool p01 = l1 > l0;  float m01 = fmaxf(l0, l1);
                bool p23 = l3 > l2;  float m23 = fmaxf(l2, l3);
                bool phi = m23 > m01;
                cr = phi ? (p23 ? crc[3] : crc[2]) : (p01 ? crc[1] : crc[0]);
                cz = phi ? (p23 ? czc[3] : czc[2]) : (p01 ? czc[1] : czc[0]);
                cn = phi ? (p23 ? cnc[3] : cnc[2]) : (p01 ? cnc[1] : cnc[0]);
            }
            if (lane < 4) lp[t4*VV + lane] = lreg;   // 64B coalesced, 1 per 4 steps
        }
    }
}

// ---------------------------------------------------------------------------
// Pass 2: NLL from stored logits + targets from gt. One block per batch elem.
// ---------------------------------------------------------------------------
__global__ void __launch_bounds__(256)
pass2_kernel(const float* __restrict__ gt)
{
    const int b   = blockIdx.x;
    const int tid = threadIdx.x;
    const float4* lp = &g_logits[(size_t)b * SQ * VV];
    const float4* g4 = (const float4*)(gt + (size_t)b * VV * SS);

    float acc = 0.f;
    for (int t4 = tid; t4 < SQ; t4 += 256) {
        float4 L0 = lp[t4*VV+0], L1 = lp[t4*VV+1], L2 = lp[t4*VV+2], L3 = lp[t4*VV+3];
        float4 X0 = g4[t4], X1 = g4[SQ + t4], X2 = g4[2*SQ + t4], X3 = g4[3*SQ + t4];
#pragma unroll
        for (int u = 0; u < 4; u++) {
            float l0 = f4c(L0,u), l1 = f4c(L1,u), l2 = f4c(L2,u), l3 = f4c(L3,u);
            float x0 = f4c(X0,u), x1 = f4c(X1,u), x2 = f4c(X2,u), x3 = f4c(X3,u);
            // target = first-max argmax of gt
            bool u01 = x1 > x0;  float t01 = fmaxf(x0, x1);
            bool u23 = x3 > x2;  float t23 = fmaxf(x2, x3);
            bool uhi = t23 > t01;
            float lt = uhi ? (u23 ? l3 : l2) : (u01 ? l1 : l0);
            // stable log-sum-exp (precise)
            float m = fmaxf(fmaxf(l0, l1), fmaxf(l2, l3));
            float s = expf(l0 - m) + expf(l1 - m) + expf(l2 - m) + expf(l3 - m);
            acc += m + logf(s) - lt;
        }
    }
    __shared__ float sred[256];
    sred[tid] = acc;
    __syncthreads();
#pragma unroll
    for (int st = 128; st > 0; st >>= 1) {
        if (tid < st) sred[tid] += sred[tid + st];
        __syncthreads();
    }
    if (tid == 0) g_loss[b] = sred[0];
}

// ---------------------------------------------------------------------------
__global__ void zero_kernel(float* __restrict__ out, long long n)
{
    long long n4 = n >> 2;
    float4* o4 = (float4*)out;
    long long i = (long long)blockIdx.x * blockDim.x + threadIdx.x;
    long long stride = (long long)gridDim.x * blockDim.x;
    float4 zz = make_float4(0.f, 0.f, 0.f, 0.f);
    for (; i < n4; i += stride) o4[i] = zz;
    if (blockIdx.x == 0 && threadIdx.x == 0)
        for (long long k = n4 << 2; k < n; k++) out[k] = 0.f;
}

__global__ void fin_kernel(float* __restrict__ out)
{
    __shared__ float s[BB];
    s[threadIdx.x] = g_loss[threadIdx.x];
    __syncthreads();
#pragma unroll
    for (int st = BB/2; st > 0; st >>= 1) {
        if ((int)threadIdx.x < st) s[threadIdx.x] += s[threadIdx.x + st];
        __syncthreads();
    }
    if (threadIdx.x == 0) out[0] = s[0] * (1.f / (float)BB);
}

// ---------------------------------------------------------------------------
extern "C" void kernel_launch(void* const* d_in, const int* in_sizes, int n_in,
                              void* d_out, int out_size)
{
    const float* gt   = (const float*)d_in[0];
    const float* eWih = (const float*)d_in[1];
    const float* eWhh = (const float*)d_in[2];
    const float* ebih = (const float*)d_in[3];
    const float* ebhh = (const float*)d_in[4];
    const float* dWih = (const float*)d_in[5];
    const float* dWhh = (const float*)d_in[6];
    const float* dbih = (const float*)d_in[7];
    const float* dbhh = (const float*)d_in[8];
    const float* oW   = (const float*)d_in[9];
    const float* ob   = (const float*)d_in[10];
    float* out = (float*)d_out;

    zero_kernel<<<512, 256>>>(out, (long long)out_size);
    rnn_kernel<<<NBLOCKS, NTHREADS>>>(gt, eWih, eWhh, ebih, ebhh,
                                      dWih, dWhh, dbih, dbhh, oW, ob);
    pass2_kernel<<<BB, 256>>>(gt);
    fin_kernel<<<1, BB>>>(out);
}

// round 7
// speedup vs baseline: 1.5616x; 1.5616x over previous
#include <cuda_runtime.h>

#define HH 16
#define VV 4
#define BB 512
#define SS 8192
#define SQ (SS/4)
#define WPB 4                 // warps per block, 1 batch element per warp
#define NTHREADS (WPB*32)     // 128
#define NBLOCKS (BB/WPB)      // 128 blocks

__device__ float  g_loss[BB];
__device__ float4 g_logits[BB*SQ*VV];   // 64 MB: [b][t4][v] -> 4 steps' logits

typedef unsigned long long u64;

__device__ __forceinline__ float tanh_ap(float x){ float y; asm("tanh.approx.f32 %0, %1;" : "=f"(y) : "f"(x)); return y; }
__device__ __forceinline__ u64 pk(float lo, float hi){ u64 d; asm("mov.b64 %0,{%1,%2};" : "=l"(d) : "f"(lo), "f"(hi)); return d; }
__device__ __forceinline__ u64 fma2(u64 a, u64 b, u64 c){ u64 d; asm("fma.rn.f32x2 %0,%1,%2,%3;" : "=l"(d) : "l"(a), "l"(b), "l"(c)); return d; }
__device__ __forceinline__ u64 add2(u64 a, u64 b){ u64 d; asm("add.rn.f32x2 %0,%1,%2;" : "=l"(d) : "l"(a), "l"(b)); return d; }
__device__ __forceinline__ float hadd(u64 a){ float x,y; asm("mov.b64 {%0,%1},%2;" : "=f"(x), "=f"(y) : "l"(a)); return x+y; }
__device__ __forceinline__ float f4c(float4 v, int u){ return u==0?v.x:(u==1?v.y:(u==2?v.z:v.w)); }

__device__ __forceinline__ void sts_f(unsigned addr, float v){
    asm volatile("st.shared.b32 [%0], %1;" :: "r"(addr), "f"(v));
}
__device__ __forceinline__ void ldh4(unsigned base, u64* hp){
    asm volatile("ld.shared.v2.b64 {%0,%1},[%2];"    : "=l"(hp[0]), "=l"(hp[1]) : "r"(base));
    asm volatile("ld.shared.v2.b64 {%0,%1},[%2+16];" : "=l"(hp[2]), "=l"(hp[3]) : "r"(base));
    asm volatile("ld.shared.v2.b64 {%0,%1},[%2+32];" : "=l"(hp[4]), "=l"(hp[5]) : "r"(base));
    asm volatile("ld.shared.v2.b64 {%0,%1},[%2+48];" : "=l"(hp[6]), "=l"(hp[7]) : "r"(base));
}
__device__ __forceinline__ void lds4f(unsigned addr, float& a, float& b, float& c, float& d){
    asm volatile("ld.shared.v4.f32 {%0,%1,%2,%3},[%4];"
                 : "=f"(a), "=f"(b), "=f"(c), "=f"(d) : "r"(addr));
}

// ---------------------------------------------------------------------------
// Fused encoder + decoder recurrence. One batch element per warp.
// h unit j = lane&15 (both half-warps replicate). ZERO shuffles in the loop:
// all cross-lane transport goes through per-warp shared memory.
// ---------------------------------------------------------------------------
__global__ void __launch_bounds__(NTHREADS, 1)
rnn_kernel(const float* __restrict__ gt,
           const float* __restrict__ eWih, const float* __restrict__ eWhh,
           const float* __restrict__ ebih, const float* __restrict__ ebhh,
           const float* __restrict__ dWih, const float* __restrict__ dWhh,
           const float* __restrict__ dbih, const float* __restrict__ dbhh,
           const float* __restrict__ oW,  const float* __restrict__ ob)
{
    __shared__ __align__(16) float sh[WPB*16];   // h broadcast
    __shared__ __align__(16) float sl[WPB*4];    // logit exchange
    const int lane = threadIdx.x & 31;
    const int w    = threadIdx.x >> 5;
    const int j    = lane & 15;
    const int b    = blockIdx.x * WPB + w;
    const unsigned hbase = (unsigned)__cvta_generic_to_shared(&sh[w*16]);
    const unsigned lbase = (unsigned)__cvta_generic_to_shared(&sl[w*4]);

    const float4* gp = (const float4*)(gt + (size_t)b * VV * SS);
    const u64 z2 = 0ULL;

    float hme = 0.f;

    // =================== ENCODER ===================
    {
        u64 wr[8], wz[8], wn[8];
#pragma unroll
        for (int p = 0; p < 8; p++) {
            wr[p] = pk(0.5f*eWhh[j*16 + 2*p],      0.5f*eWhh[j*16 + 2*p+1]);
            wz[p] = pk(0.5f*eWhh[(16+j)*16 + 2*p], 0.5f*eWhh[(16+j)*16 + 2*p+1]);
            wn[p] = pk(0.5f*eWhh[(32+j)*16 + 2*p], 0.5f*eWhh[(32+j)*16 + 2*p+1]);
        }
        const u64 xr01 = pk(0.5f*eWih[j*4+0],      0.5f*eWih[j*4+1]);
        const u64 xr23 = pk(0.5f*eWih[j*4+2],      0.5f*eWih[j*4+3]);
        const u64 xz01 = pk(0.5f*eWih[(16+j)*4+0], 0.5f*eWih[(16+j)*4+1]);
        const u64 xz23 = pk(0.5f*eWih[(16+j)*4+2], 0.5f*eWih[(16+j)*4+3]);
        const u64 xn01 = pk(     eWih[(32+j)*4+0],      eWih[(32+j)*4+1]);
        const u64 xn23 = pk(     eWih[(32+j)*4+2],      eWih[(32+j)*4+3]);
        const u64 brpk  = pk(0.5f*(ebih[j]    + ebhh[j]),    0.f);
        const u64 bzpk  = pk(0.5f*(ebih[16+j] + ebhh[16+j]), 0.f);
        const u64 binpk = pk(ebih[32+j], 0.f);
        const u64 bhnpk = pk(0.5f*ebhh[32+j], 0.f);

        u64 hp[8];
#pragma unroll
        for (int p = 0; p < 8; p++) hp[p] = 0ULL;   // h0 = 0

        float4 c0 = gp[0], c1 = gp[SQ], c2 = gp[2*SQ], c3 = gp[3*SQ];

        for (int t4 = 0; t4 < SQ; ++t4) {
            int tn = t4 + 1 < SQ ? t4 + 1 : t4;
            float4 nx0 = gp[tn], nx1 = gp[SQ + tn], nx2 = gp[2*SQ + tn], nx3 = gp[3*SQ + tn];
#pragma unroll
            for (int u = 0; u < 4; u++) {
                u64 px01 = pk(f4c(c0,u), f4c(c1,u));
                u64 px23 = pk(f4c(c2,u), f4c(c3,u));
                u64 ri0 = fma2(px01, xr01, brpk);
                u64 ri1 = fma2(px23, xr23, z2);
                u64 zi0 = fma2(px01, xz01, bzpk);
                u64 zi1 = fma2(px23, xz23, z2);
                float gin = hadd(fma2(px23, xn23, fma2(px01, xn01, binpk)));

                u64 r0 = fma2(hp[0], wr[0], ri0); r0 = fma2(hp[4], wr[4], r0);
                u64 r1 = fma2(hp[1], wr[1], ri1); r1 = fma2(hp[5], wr[5], r1);
                u64 r2 = fma2(hp[2], wr[2], z2);  r2 = fma2(hp[6], wr[6], r2);
                u64 r3 = fma2(hp[3], wr[3], z2);  r3 = fma2(hp[7], wr[7], r3);
                float sr = hadd(add2(add2(r0,r1), add2(r2,r3)));

                u64 q0 = fma2(hp[0], wz[0], zi0); q0 = fma2(hp[4], wz[4], q0);
                u64 q1 = fma2(hp[1], wz[1], zi1); q1 = fma2(hp[5], wz[5], q1);
                u64 q2 = fma2(hp[2], wz[2], z2);  q2 = fma2(hp[6], wz[6], q2);
                u64 q3 = fma2(hp[3], wz[3], z2);  q3 = fma2(hp[7], wz[7], q3);
                float sz = hadd(add2(add2(q0,q1), add2(q2,q3)));

                u64 n0a = fma2(hp[0], wn[0], bhnpk); n0a = fma2(hp[4], wn[4], n0a);
                u64 n1a = fma2(hp[1], wn[1], z2);    n1a = fma2(hp[5], wn[5], n1a);
                u64 n2a = fma2(hp[2], wn[2], z2);    n2a = fma2(hp[6], wn[6], n2a);
                u64 n3a = fma2(hp[3], wn[3], z2);    n3a = fma2(hp[7], wn[7], n3a);
                float ghn = hadd(add2(add2(n0a,n1a), add2(n2a,n3a)));

                float tr  = tanh_ap(sr);
                float tz  = tanh_ap(sz);
                float zg  = fmaf(tz,  0.5f, 0.5f);
                float omz = fmaf(tz, -0.5f, 0.5f);
                float zh  = zg * hme;
                float n = tanh_ap(fmaf(tr, ghn, gin + ghn));
                hme = fmaf(n, omz, zh);
                if (lane < 16) sts_f(hbase + j*4, hme);
                ldh4(hbase, hp);
            }
            c0 = nx0; c1 = nx1; c2 = nx2; c3 = nx3;
        }
    }

    // =================== DECODER ===================
    {
        const int v = j & 3;
        u64 wr[8], wz[8], wn[8], ow[8];
#pragma unroll
        for (int p = 0; p < 8; p++) {
            wr[p] = pk(0.5f*dWhh[j*16 + 2*p],      0.5f*dWhh[j*16 + 2*p+1]);
            wz[p] = pk(0.5f*dWhh[(16+j)*16 + 2*p], 0.5f*dWhh[(16+j)*16 + 2*p+1]);
            wn[p] = pk(0.5f*dWhh[(32+j)*16 + 2*p], 0.5f*dWhh[(32+j)*16 + 2*p+1]);
            ow[p] = pk(oW[v*16 + 2*p], oW[v*16 + 2*p+1]);
        }
        const float br   = 0.5f*(dbih[j]    + dbhh[j]);
        const float bz   = 0.5f*(dbih[16+j] + dbhh[16+j]);
        const float bin_ = dbih[32+j];
        const u64 bhnpk  = pk(0.5f*dbhh[32+j], 0.f);
        const u64 obpk   = pk(ob[v], 0.f);

        float crc[4], czc[4], cnc[4];
#pragma unroll
        for (int c = 0; c < 4; c++) {
            crc[c] = br   + 0.5f*dWih[j*4 + c];
            czc[c] = bz   + 0.5f*dWih[(16+j)*4 + c];
            cnc[c] = bin_ +      dWih[(32+j)*4 + c];
        }
        float cr = br, cz = bz, cn = bin_;     // t=0: x = 0

        u64 hp[8];
        if (lane < 16) sts_f(hbase + j*4, hme);
        ldh4(hbase, hp);                       // hp = enc hidden

        float4* lp = &g_logits[(size_t)b * SQ * VV];
        float4 lreg;

        for (int t4 = 0; t4 < SQ; ++t4) {
#pragma unroll
            for (int u = 0; u < 4; u++) {
                // gates from hp = h_t
                u64 r0 = fma2(hp[0], wr[0], z2); r0 = fma2(hp[4], wr[4], r0);
                u64 r1 = fma2(hp[1], wr[1], z2); r1 = fma2(hp[5], wr[5], r1);
                u64 r2 = fma2(hp[2], wr[2], z2); r2 = fma2(hp[6], wr[6], r2);
                u64 r3 = fma2(hp[3], wr[3], z2); r3 = fma2(hp[7], wr[7], r3);
                float sr = hadd(add2(add2(r0,r1), add2(r2,r3))) + cr;

                u64 q0 = fma2(hp[0], wz[0], z2); q0 = fma2(hp[4], wz[4], q0);
                u64 q1 = fma2(hp[1], wz[1], z2); q1 = fma2(hp[5], wz[5], q1);
                u64 q2 = fma2(hp[2], wz[2], z2); q2 = fma2(hp[6], wz[6], q2);
                u64 q3 = fma2(hp[3], wz[3], z2); q3 = fma2(hp[7], wz[7], q3);
                float sz = hadd(add2(add2(q0,q1), add2(q2,q3))) + cz;

                u64 n0 = fma2(hp[0], wn[0], bhnpk); n0 = fma2(hp[4], wn[4], n0);
                u64 n1 = fma2(hp[1], wn[1], z2);    n1 = fma2(hp[5], wn[5], n1);
                u64 n2 = fma2(hp[2], wn[2], z2);    n2 = fma2(hp[6], wn[6], n2);
                u64 n3 = fma2(hp[3], wn[3], z2);    n3 = fma2(hp[7], wn[7], n3);
                float ghn = hadd(add2(add2(n0,n1), add2(n2,n3)));

                float tr  = tanh_ap(sr);
                float tz  = tanh_ap(sz);
                float zg  = fmaf(tz,  0.5f, 0.5f);
                float omz = fmaf(tz, -0.5f, 0.5f);
                float zh  = zg * hme;
                float n = tanh_ap(fmaf(tr, ghn, cn + ghn));
                hme = fmaf(n, omz, zh);
                if (lane < 16) sts_f(hbase + j*4, hme);
                ldh4(hbase, hp);                 // hp = h_{t+1}

                // logit for class v from fresh hp
                u64 o0 = fma2(hp[0], ow[0], obpk); o0 = fma2(hp[4], ow[4], o0);
                u64 o1 = fma2(hp[1], ow[1], z2);   o1 = fma2(hp[5], ow[5], o1);
                u64 o2 = fma2(hp[2], ow[2], z2);   o2 = fma2(hp[6], ow[6], o2);
                u64 o3 = fma2(hp[3], ow[3], z2);   o3 = fma2(hp[7], ow[7], o3);
                float outv = hadd(add2(add2(o0,o1), add2(o2,o3)));

                // exchange 4 logits via smem (NO shuffles): lanes 0-3 store,
                // all lanes read one 16B broadcast load.
                if (lane < 4) sts_f(lbase + lane*4, outv);
                float l0, l1, l2, l3;
                lds4f(lbase, l0, l1, l2, l3);

                if (u == 0) lreg.x = outv;
                else if (u == 1) lreg.y = outv;
                else if (u == 2) lreg.z = outv;
                else lreg.w = outv;

                // argmax (first-max) -> feedback select
                bool p01 = l1 > l0;  float m01 = fmaxf(l0, l1);
                bool p23 = l3 > l2;  float m23 = fmaxf(l2, l3);
                bool phi = m23 > m01;
                cr = phi ? (p23 ? crc[3] : crc[2]) : (p01 ? crc[1] : crc[0]);
                cz = phi ? (p23 ? czc[3] : czc[2]) : (p01 ? czc[1] : czc[0]);
                cn = phi ? (p23 ? cnc[3] : cnc[2]) : (p01 ? cnc[1] : cnc[0]);
            }
            if (lane < 4) lp[t4*VV + lane] = lreg;   // 64B coalesced, 1 per 4 steps
        }
    }
}

// ---------------------------------------------------------------------------
// Pass 2: NLL from stored logits + targets from gt. One block per batch elem.
// ---------------------------------------------------------------------------
__global__ void __launch_bounds__(256)
pass2_kernel(const float* __restrict__ gt)
{
    const int b   = blockIdx.x;
    const int tid = threadIdx.x;
    const float4* lp = &g_logits[(size_t)b * SQ * VV];
    const float4* g4 = (const float4*)(gt + (size_t)b * VV * SS);

    float acc = 0.f;
    for (int t4 = tid; t4 < SQ; t4 += 256) {
        float4 L0 = lp[t4*VV+0], L1 = lp[t4*VV+1], L2 = lp[t4*VV+2], L3 = lp[t4*VV+3];
        float4 X0 = g4[t4], X1 = g4[SQ + t4], X2 = g4[2*SQ + t4], X3 = g4[3*SQ + t4];
#pragma unroll
        for (int u = 0; u < 4; u++) {
            float l0 = f4c(L0,u), l1 = f4c(L1,u), l2 = f4c(L2,u), l3 = f4c(L3,u);
            float x0 = f4c(X0,u), x1 = f4c(X1,u), x2 = f4c(X2,u), x3 = f4c(X3,u);
            bool u01 = x1 > x0;  float t01 = fmaxf(x0, x1);
            bool u23 = x3 > x2;  float t23 = fmaxf(x2, x3);
            bool uhi = t23 > t01;
            float lt = uhi ? (u23 ? l3 : l2) : (u01 ? l1 : l0);
            float m = fmaxf(fmaxf(l0, l1), fmaxf(l2, l3));
            float s = expf(l0 - m) + expf(l1 - m) + expf(l2 - m) + expf(l3 - m);
            acc += m + logf(s) - lt;
        }
    }
    __shared__ float sred[256];
    sred[tid] = acc;
    __syncthreads();
#pragma unroll
    for (int st = 128; st > 0; st >>= 1) {
        if (tid < st) sred[tid] += sred[tid + st];
        __syncthreads();
    }
    if (tid == 0) g_loss[b] = sred[0];
}

// ---------------------------------------------------------------------------
__global__ void zero_kernel(float* __restrict__ out, long long n)
{
    long long n4 = n >> 2;
    float4* o4 = (float4*)out;
    long long i = (long long)blockIdx.x * blockDim.x + threadIdx.x;
    long long stride = (long long)gridDim.x * blockDim.x;
    float4 zz = make_float4(0.f, 0.f, 0.f, 0.f);
    for (; i < n4; i += stride) o4[i] = zz;
    if (blockIdx.x == 0 && threadIdx.x == 0)
        for (long long k = n4 << 2; k < n; k++) out[k] = 0.f;
}

__global__ void fin_kernel(float* __restrict__ out)
{
    __shared__ float s[BB];
    s[threadIdx.x] = g_loss[threadIdx.x];
    __syncthreads();
#pragma unroll
    for (int st = BB/2; st > 0; st >>= 1) {
        if ((int)threadIdx.x < st) s[threadIdx.x] += s[threadIdx.x + st];
        __syncthreads();
    }
    if (threadIdx.x == 0) out[0] = s[0] * (1.f / (float)BB);
}

// ---------------------------------------------------------------------------
extern "C" void kernel_launch(void* const* d_in, const int* in_sizes, int n_in,
                              void* d_out, int out_size)
{
    const float* gt   = (const float*)d_in[0];
    const float* eWih = (const float*)d_in[1];
    const float* eWhh = (const float*)d_in[2];
    const float* ebih = (const float*)d_in[3];
    const float* ebhh = (const float*)d_in[4];
    const float* dWih = (const float*)d_in[5];
    const float* dWhh = (const float*)d_in[6];
    const float* dbih = (const float*)d_in[7];
    const float* dbhh = (const float*)d_in[8];
    const float* oW   = (const float*)d_in[9];
    const float* ob   = (const float*)d_in[10];
    float* out = (float*)d_out;

    zero_kernel<<<512, 256>>>(out, (long long)out_size);
    rnn_kernel<<<NBLOCKS, NTHREADS>>>(gt, eWih, eWhh, ebih, ebhh,
                                      dWih, dWhh, dbih, dbhh, oW, ob);
    pass2_kernel<<<BB, 256>>>(gt);
    fin_kernel<<<1, BB>>>(out);
}